// round 17
// baseline (speedup 1.0000x reference)
#include <cuda_runtime.h>
#include <cstdint>

#define BB 1024      // batch
#define DD 512       // feature dim
#define MM 256       // modes
#define THRESHV 1.0f
#define RB 8         // batch rows per scores-block
#define KSPLIT 4     // k-quarters for scores gemm
#define KQ4 32       // float4 per k-quarter (128 floats)
#define LB 8         // load batch (MLP group) in fused kernel
#define WTS 257      // padded Wt row stride (floats): 256 modes + 1

// logit partials per k-quarter: [kq][b][m], 4 MB
__device__ float g_logitsP[KSPLIT][BB * MM];

// ---------------------------------------------------------------------------
// Kernel 1a (UNCHANGED from R16): logit partials.
// grid (128 row-groups, 4 k-quarters) x 1024 thr, 2 blocks/SM.
// ---------------------------------------------------------------------------
__global__ __launch_bounds__(1024, 2)
void poly_scores_gemm(const float* __restrict__ x,
                      const float* __restrict__ W)
{
    __shared__ float  Wt[16 * WTS];            // 16 k-slots x 257 floats
    __shared__ float4 xs[RB * KQ4];            // 8 rows x 32 float4 (k-quarter)

    const int b0 = blockIdx.x * RB;
    const int kq = blockIdx.y;                 // k-quarter
    const int t  = threadIdx.x;                // 0..1023
    const int m  = t & 255;                    // mode
    const int g  = t >> 8;                     // row group -> rows 2g, 2g+1

    if (t < RB * KQ4) {
        const int r = t >> 5;
        const int j = t & 31;
        xs[t] = reinterpret_cast<const float4*>(x)[(size_t)(b0 + r) * (DD / 4) + kq * KQ4 + j];
    }

    const int sm = t >> 2;
    const int sj = t & 3;
    const float4* Wg = reinterpret_cast<const float4*>(W);
    const size_t wbase = (size_t)sm * (DD / 4) + kq * KQ4 + sj;

    float a0 = 0.0f, a1 = 0.0f;
    float4 v = Wg[wbase];                      // prefetch tile 0

    const float4* xr0 = &xs[(2 * g)     * KQ4];
    const float4* xr1 = &xs[(2 * g + 1) * KQ4];

    #pragma unroll 1
    for (int tile = 0; tile < 8; ++tile) {     // 8 tiles of 16 k-floats
        __syncthreads();
        Wt[(sj * 4 + 0) * WTS + sm] = v.x;
        Wt[(sj * 4 + 1) * WTS + sm] = v.y;
        Wt[(sj * 4 + 2) * WTS + sm] = v.z;
        Wt[(sj * 4 + 3) * WTS + sm] = v.w;
        if (tile < 7) v = Wg[wbase + (tile + 1) * 4];
        __syncthreads();

        #pragma unroll
        for (int kk = 0; kk < 4; ++kk) {
            const float w0 = Wt[(kk * 4 + 0) * WTS + m];
            const float w1 = Wt[(kk * 4 + 1) * WTS + m];
            const float w2 = Wt[(kk * 4 + 2) * WTS + m];
            const float w3 = Wt[(kk * 4 + 3) * WTS + m];
            const float4 xv0 = xr0[tile * 4 + kk];
            const float4 xv1 = xr1[tile * 4 + kk];
            a0 = fmaf(w0, xv0.x, a0); a0 = fmaf(w1, xv0.y, a0);
            a0 = fmaf(w2, xv0.z, a0); a0 = fmaf(w3, xv0.w, a0);
            a1 = fmaf(w0, xv1.x, a1); a1 = fmaf(w1, xv1.y, a1);
            a1 = fmaf(w2, xv1.z, a1); a1 = fmaf(w3, xv1.w, a1);
        }
    }

    g_logitsP[kq][(size_t)(b0 + 2 * g)     * MM + m] = a0;
    g_logitsP[kq][(size_t)(b0 + 2 * g + 1) * MM + m] = a1;
}

// ---------------------------------------------------------------------------
// Kernel 1b (UNCHANGED from R16): sum partials (+bias), softmax -> scores.
// ---------------------------------------------------------------------------
__global__ __launch_bounds__(256)
void poly_scores_softmax(const float* __restrict__ bias,
                         float* __restrict__ scores)
{
    __shared__ float logits[RB][MM];

    const int b0 = blockIdx.x * RB;
    const int t  = threadIdx.x;                // 0..255 == mode

    const float bv = bias[t];
    #pragma unroll
    for (int r = 0; r < RB; ++r) {
        const size_t i = (size_t)(b0 + r) * MM + t;
        logits[r][t] = ((g_logitsP[0][i] + g_logitsP[1][i])
                      + g_logitsP[2][i]) + g_logitsP[3][i] + bv;
    }
    __syncthreads();

    const int w    = t >> 5;
    const int lane = t & 31;
    float vv[8];
    float mx = -1e30f;
    #pragma unroll
    for (int j = 0; j < 8; ++j) { vv[j] = logits[w][lane + 32 * j]; mx = fmaxf(mx, vv[j]); }
    #pragma unroll
    for (int o = 16; o > 0; o >>= 1) mx = fmaxf(mx, __shfl_xor_sync(0xFFFFFFFFu, mx, o));
    float s = 0.0f;
    #pragma unroll
    for (int j = 0; j < 8; ++j) { vv[j] = __expf(vv[j] - mx); s += vv[j]; }
    #pragma unroll
    for (int o = 16; o > 0; o >>= 1) s += __shfl_xor_sync(0xFFFFFFFFu, s, o);
    const float inv = 1.0f / s;

    float* srow = scores + (size_t)(b0 + w) * MM;
    #pragma unroll
    for (int j = 0; j < 8; ++j) srow[lane + 32 * j] = vv[j] * inv;
}

// ---------------------------------------------------------------------------
// Kernel 2 (NEW): float2 granularity, NO mode chunking, NO partials.
// grid (1024 b, 2 d-halves) x 128 threads = 262144 threads -> ~80% occ
// (vs 43% ceiling at float4 granularity). Each thread owns one (b, float2)
// slot for ALL 256 modes: mixed accumulates fully in-register, written once.
// LB=8 batched streaming loads keep 2KB/warp in flight. beta table in smem
// (same i/257.0f op -> bitwise identical) avoids 256 per-thread divisions.
// ---------------------------------------------------------------------------
__global__ __launch_bounds__(128)
void poly_fused_kernel(const float* __restrict__ x,
                       const float* __restrict__ mem,
                       const float* __restrict__ scores,
                       float* __restrict__ mixed,
                       float* __restrict__ mem_new)
{
    __shared__ float s_sc[MM];
    __shared__ float s_beta[MM];

    const int b = blockIdx.x;
    const int h = blockIdx.y;                  // d-half 0..1
    const int t = threadIdx.x;                 // 0..127

    #pragma unroll
    for (int i = t; i < MM; i += 128) {
        s_sc[i]   = scores[(size_t)b * MM + i];
        s_beta[i] = (float)i / 257.0f;
    }
    __syncthreads();

    const size_t base = (size_t)b * (DD / 2) + (size_t)h * 128 + t;  // float2 units
    const float2 xv   = reinterpret_cast<const float2*>(x)[base];

    const float2* m2 = reinterpret_cast<const float2*>(mem);
    float2*       o2 = reinterpret_cast<float2*>(mem_new);

    float2 acc = make_float2(0.f, 0.f);
    const size_t stride = (size_t)BB * (DD / 2);    // float2 per mode

    #pragma unroll 1
    for (int mo = 0; mo < MM; mo += LB) {
        float2 mv[LB];
        #pragma unroll
        for (int j = 0; j < LB; ++j)
            mv[j] = __ldcs(m2 + base + (size_t)(mo + j) * stride);

        #pragma unroll
        for (int j = 0; j < LB; ++j) {
            const float beta = s_beta[mo + j];

            float2 mn;
            mn.x = fmaf(beta, mv[j].x, xv.x) - (mv[j].x > THRESHV ? 1.0f : 0.0f);
            mn.y = fmaf(beta, mv[j].y, xv.y) - (mv[j].y > THRESHV ? 1.0f : 0.0f);

            __stcs(o2 + base + (size_t)(mo + j) * stride, mn);

            const float sc = s_sc[mo + j];
            acc.x += (mn.x - THRESHV > 0.0f) ? sc : 0.0f;
            acc.y += (mn.y - THRESHV > 0.0f) ? sc : 0.0f;
        }
    }

    reinterpret_cast<float2*>(mixed)[base] = acc;
}

// ---------------------------------------------------------------------------
// Launch: outputs packed as [mixed (B*D) | mem_new (M*B*D) | scores (B*M)]
// ---------------------------------------------------------------------------
extern "C" void kernel_launch(void* const* d_in, const int* in_sizes, int n_in,
                              void* d_out, int out_size)
{
    const float* x    = (const float*)d_in[0];   // [B, D]
    const float* mem  = (const float*)d_in[1];   // [M, B, D]
    const float* W    = (const float*)d_in[2];   // [M, D]
    const float* bias = (const float*)d_in[3];   // [M]

    float* out     = (float*)d_out;
    float* mixed   = out;                                          // B*D
    float* mem_new = out + (size_t)BB * DD;                        // M*B*D
    float* scores  = out + (size_t)BB * DD + (size_t)MM * BB * DD; // B*M

    poly_scores_gemm<<<dim3(BB / RB, KSPLIT), 1024>>>(x, W);
    poly_scores_softmax<<<BB / RB, 256>>>(bias, scores);
    poly_fused_kernel<<<dim3(BB, 2), 128>>>(x, mem, scores, mixed, mem_new);
}